// round 3
// baseline (speedup 1.0000x reference)
#include <cuda_runtime.h>
#include <math.h>
#include <stdint.h>

// Problem constants
#define BB   32
#define NN_  1024
#define DD   256
#define HH   256
#define EE   256
#define CC   256
#define KTOP 128
#define TEMPR 0.1f

// ---------------- scratch (device globals; no allocation allowed) ----------------
__device__ float g_deg[BB * NN_];            // 128 KB
__device__ float g_agg[BB * NN_ * DD];       // 32 MB
__device__ float g_pre[BB * NN_ * HH];       // 32 MB
__device__ float g_sTa[BB * CC * NN_];       // 32 MB
__device__ float g_sts[BB * CC * CC];        // 8 MB
__device__ float g_U[BB * CC * CC];          // 8 MB
__device__ float g_V[BB * CC * CC];          // 8 MB
__device__ float g_scores[BB * CC];
__device__ float g_thresh[BB];
__device__ double g_sumsq_adj;
__device__ double g_ent;
__device__ double g_trA[BB], g_ssA[BB], g_trG[BB], g_ssG[BB], g_dotUV[BB];

// ---------------- helpers ----------------
__device__ __forceinline__ double block_red_d(double v, double* sm) {
    int t = threadIdx.x;
    sm[t] = v; __syncthreads();
    for (int o = 128; o > 0; o >>= 1) {
        if (t < o) sm[t] += sm[t + o];
        __syncthreads();
    }
    double r = sm[0]; __syncthreads();
    return r;
}

__global__ void init_kernel() {
    int i = blockIdx.x * blockDim.x + threadIdx.x;
    if (i < BB * CC) g_scores[i] = 0.0f;
    if (i == 0) { g_sumsq_adj = 0.0; g_ent = 0.0; }
}

// degree: deg[b,n] = max(1, sum_m adj[b,n,m])
__global__ void deg_kernel(const float* __restrict__ adj) {
    int row = blockIdx.x;                    // b*N + n
    const float* a = adj + (size_t)row * NN_;
    float s = 0.f;
    for (int i = threadIdx.x; i < NN_; i += 256) s += a[i];
    __shared__ float sm[256];
    sm[threadIdx.x] = s; __syncthreads();
    for (int o = 128; o > 0; o >>= 1) {
        if (threadIdx.x < o) sm[threadIdx.x] += sm[threadIdx.x + o];
        __syncthreads();
    }
    if (threadIdx.x == 0) g_deg[row] = fmaxf(sm[0], 1.0f);
}

// ---------------- tiled SGEMM: C = op(A)@B  [+bias][/rowdiv][+=C] ----------------
// TA=false: A is [M,K] row-major (lda=K).  TA=true: A is [K,M] row-major (lda=M).
// B is [K,N] row-major. 64x64 tile, BK=16, 256 threads, 4x4 microtile.
template<bool TA>
__global__ __launch_bounds__(256) void gemm_kernel(
    const float* __restrict__ A, const float* __restrict__ Bm, float* __restrict__ Cm,
    const float* __restrict__ bias, const float* __restrict__ rowdiv,
    int M, int Nn, int Kd, size_t sA, size_t sB, size_t sC, int beta)
{
    int bz = blockIdx.z;
    A  += (size_t)bz * sA;
    Bm += (size_t)bz * sB;
    Cm += (size_t)bz * sC;
    int bm = blockIdx.y * 64, bn = blockIdx.x * 64;
    int tid = threadIdx.x, tx = tid & 15, ty = tid >> 4;

    __shared__ float As[16][68];   // [k][m], +4 pad keeps 16B row alignment
    __shared__ float Bs[16][64];   // [k][n]

    float acc[4][4] = {};

    for (int k0 = 0; k0 < Kd; k0 += 16) {
        if (TA) {
            int rr = tid >> 6, cc = tid & 63;
            #pragma unroll
            for (int i = 0; i < 4; i++)
                As[rr + 4 * i][cc] = A[(size_t)(k0 + rr + 4 * i) * M + bm + cc];
        } else {
            int c = tid & 15, r0 = tid >> 4;
            #pragma unroll
            for (int i = 0; i < 4; i++)
                As[c][r0 + 16 * i] = A[(size_t)(bm + r0 + 16 * i) * Kd + k0 + c];
        }
        {
            int rr = tid >> 6, cc = tid & 63;
            #pragma unroll
            for (int i = 0; i < 4; i++)
                Bs[rr + 4 * i][cc] = Bm[(size_t)(k0 + rr + 4 * i) * Nn + bn + cc];
        }
        __syncthreads();

        #pragma unroll
        for (int kk = 0; kk < 16; kk++) {
            float4 a4 = *(const float4*)&As[kk][ty * 4];
            float4 b4 = *(const float4*)&Bs[kk][tx * 4];
            float av[4] = {a4.x, a4.y, a4.z, a4.w};
            float bv[4] = {b4.x, b4.y, b4.z, b4.w};
            #pragma unroll
            for (int i = 0; i < 4; i++)
                #pragma unroll
                for (int j = 0; j < 4; j++)
                    acc[i][j] += av[i] * bv[j];
        }
        __syncthreads();
    }

    #pragma unroll
    for (int i = 0; i < 4; i++) {
        int m = bm + ty * 4 + i;
        float rd = rowdiv ? rowdiv[(size_t)bz * M + m] : 1.0f;
        #pragma unroll
        for (int j = 0; j < 4; j++) {
            int n = bn + tx * 4 + j;
            float v = acc[i][j];
            if (rowdiv) v /= rd;
            if (bias)   v += bias[n];
            size_t idx = (size_t)m * Nn + n;
            if (beta)   v += Cm[idx];
            Cm[idx] = v;
        }
    }
}

// l2-normalize row (len 256) then relu, in place: h = relu(x) / max(||x||, 1e-12)
__global__ void normrelu_kernel(float* __restrict__ p) {
    size_t row = blockIdx.x;
    float* r = p + row * HH;
    float v = r[threadIdx.x];
    __shared__ float sm[256];
    sm[threadIdx.x] = v * v; __syncthreads();
    for (int o = 128; o > 0; o >>= 1) {
        if (threadIdx.x < o) sm[threadIdx.x] += sm[threadIdx.x + o];
        __syncthreads();
    }
    float nrm = fmaxf(sqrtf(sm[0]), 1e-12f);
    r[threadIdx.x] = fmaxf(v, 0.0f) / nrm;
}

// softmax over last dim (256), in place
__global__ void softmax_kernel(float* __restrict__ s) {
    size_t row = blockIdx.x;
    float* r = s + row * CC;
    float v = r[threadIdx.x];
    __shared__ float sm[256];
    sm[threadIdx.x] = v; __syncthreads();
    for (int o = 128; o > 0; o >>= 1) {
        if (threadIdx.x < o) sm[threadIdx.x] = fmaxf(sm[threadIdx.x], sm[threadIdx.x + o]);
        __syncthreads();
    }
    float mx = sm[0]; __syncthreads();
    float e = expf(v - mx);
    sm[threadIdx.x] = e; __syncthreads();
    for (int o = 128; o > 0; o >>= 1) {
        if (threadIdx.x < o) sm[threadIdx.x] += sm[threadIdx.x + o];
        __syncthreads();
    }
    r[threadIdx.x] = e / sm[0];
}

// scores[b,c] = sum_n s[b,n,c]   grid: (8, B), thread = column
__global__ void colsum_kernel(const float* __restrict__ s) {
    int b = blockIdx.y;
    const float* base = s + ((size_t)b * NN_ + (size_t)blockIdx.x * 128) * CC;
    float acc = 0.f;
    for (int r = 0; r < 128; r++) acc += base[(size_t)r * CC + threadIdx.x];
    atomicAdd(&g_scores[b * CC + threadIdx.x], acc);
}

// thresh[b] = K-th largest of scores[b,:]
__global__ void topk_kernel() {
    int b = blockIdx.x, t = threadIdx.x;
    __shared__ float sm[256];
    sm[t] = g_scores[b * CC + t]; __syncthreads();
    float v = sm[t];
    int cnt = 0;
    for (int j = 0; j < CC; j++) {
        float w = sm[j];
        cnt += (w > v) || (w == v && j < t);
    }
    if (cnt == KTOP - 1) g_thresh[b] = v;
}

// s *= sigmoid((scores - thresh)/T), accumulate entropy  grid: (8, B)
__global__ void gate_kernel(float* __restrict__ s) {
    int b = blockIdx.y, t = threadIdx.x;
    float xg = (g_scores[b * CC + t] - g_thresh[b]) / TEMPR;
    float gt;
    if (xg >= 0.f) gt = 1.0f / (1.0f + expf(-xg));
    else { float ex = expf(xg); gt = ex / (1.0f + ex); }
    float* base = s + ((size_t)b * NN_ + (size_t)blockIdx.x * 128) * CC;
    double e = 0.0;
    for (int r = 0; r < 128; r++) {
        size_t idx = (size_t)r * CC + t;
        float v = base[idx] * gt;
        base[idx] = v;
        e += (double)(-v * logf(v + 1e-15f));
    }
    __shared__ double sm[256];
    double tot = block_red_d(e, sm);
    if (t == 0) atomicAdd(&g_ent, tot);
}

// global sum of adj^2 (double)
__global__ void sumsq_kernel(const float* __restrict__ adj, size_t n) {
    double acc = 0.0;
    for (size_t i = (size_t)blockIdx.x * blockDim.x + threadIdx.x; i < n;
         i += (size_t)gridDim.x * blockDim.x) {
        float v = adj[i];
        acc += (double)v * v;
    }
    __shared__ double sm[256];
    double tot = block_red_d(acc, sm);
    if (threadIdx.x == 0) atomicAdd(&g_sumsq_adj, tot);
}

// per-batch traces / frobenius sums over [C,C] mats: adj_p, sts, U.V
__global__ void batchred_kernel(const float* __restrict__ adjp) {
    int b = blockIdx.x, t = threadIdx.x;
    const float* P = adjp  + (size_t)b * CC * CC;
    const float* G = g_sts + (size_t)b * CC * CC;
    const float* U = g_U   + (size_t)b * CC * CC;
    const float* V = g_V   + (size_t)b * CC * CC;
    double trA = 0, ssA = 0, trG = 0, ssG = 0, duv = 0;
    for (int i = t; i < CC * CC; i += 256) {
        float p = P[i]; ssA += (double)p * p;
        float g = G[i]; ssG += (double)g * g;
        duv += (double)U[i] * (double)V[i];
        if (i % (CC + 1) == 0) { trA += p; trG += g; }
    }
    __shared__ double sm[256];
    double r;
    r = block_red_d(trA, sm); if (t == 0) g_trA[b] = r;
    r = block_red_d(ssA, sm); if (t == 0) g_ssA[b] = r;
    r = block_red_d(trG, sm); if (t == 0) g_trG[b] = r;
    r = block_red_d(ssG, sm); if (t == 0) g_ssG[b] = r;
    r = block_red_d(duv, sm); if (t == 0) g_dotUV[b] = r;
}

// final scalars: link, ent, clu, recon
__global__ void final_kernel(float* __restrict__ o) {
    double linksq = g_sumsq_adj, reconsq = g_sumsq_adj, clusum = 0.0;
    for (int b = 0; b < BB; b++) {
        linksq  += -2.0 * g_trA[b] + g_ssG[b];
        reconsq += -2.0 * g_ssA[b] + g_dotUV[b];
        double nrm = sqrt(g_ssG[b]); if (nrm < 1e-12) nrm = 1e-12;
        double t1 = g_ssG[b] / (nrm * nrm);
        double cb = t1 - 2.0 * g_trG[b] / (nrm * 16.0) + 1.0;   // sqrt(C)=16
        clusum += sqrt(cb > 0.0 ? cb : 0.0);
    }
    double sz = (double)BB * NN_ * NN_;
    o[0] = (float)(sqrt(linksq  > 0.0 ? linksq  : 0.0) / sz);  // link
    o[1] = (float)(g_ent / ((double)BB * NN_));                // ent
    o[2] = (float)(clusum / BB);                               // clu
    o[3] = (float)(sqrt(reconsq > 0.0 ? reconsq : 0.0) / sz);  // recon
}

// ---------------- launch ----------------
extern "C" void kernel_launch(void* const* d_in, const int* in_sizes, int n_in,
                              void* d_out, int out_size) {
    const float* x    = (const float*)d_in[0];
    const float* adj  = (const float*)d_in[1];
    const float* Wr_p = (const float*)d_in[2];
    const float* br_p = (const float*)d_in[3];
    const float* Wo_p = (const float*)d_in[4];
    const float* Wl_p = (const float*)d_in[5];
    const float* bl_p = (const float*)d_in[6];
    const float* Wr_e = (const float*)d_in[7];
    const float* br_e = (const float*)d_in[8];
    const float* Wo_e = (const float*)d_in[9];
    const float* Wl_e = (const float*)d_in[10];
    const float* bl_e = (const float*)d_in[11];

    float* out       = (float*)d_out;
    float* out_xp    = out;                         // [B,C,E]
    float* out_adjp  = out + 2097152;               // [B,C,C]
    float* out_s     = out + 4194304;               // [B,N,C]
    float* out_scal  = out + 12582912;              // link, ent, clu, recon
    float* out_nodex = out + 12582916;              // [B,N,E]

    float *p_deg, *p_agg, *p_pre, *p_sTa, *p_sts, *p_U, *p_V;
    cudaGetSymbolAddress((void**)&p_deg, g_deg);
    cudaGetSymbolAddress((void**)&p_agg, g_agg);
    cudaGetSymbolAddress((void**)&p_pre, g_pre);
    cudaGetSymbolAddress((void**)&p_sTa, g_sTa);
    cudaGetSymbolAddress((void**)&p_sts, g_sts);
    cudaGetSymbolAddress((void**)&p_U,   g_U);
    cudaGetSymbolAddress((void**)&p_V,   g_V);

    init_kernel<<<32, 256>>>();
    deg_kernel<<<BB * NN_, 256>>>(adj);

    // agg = (adj @ x) / deg   batched: M=N=1024, Nn=D, K=N
    gemm_kernel<false><<<dim3(DD / 64, NN_ / 64, BB), 256>>>(
        adj, x, p_agg, nullptr, p_deg,
        NN_, DD, NN_, (size_t)NN_ * NN_, (size_t)NN_ * DD, (size_t)NN_ * DD, 0);

    // ---- embed branch: node_x = relu(l2n(agg@Wr_e + x@Wo_e + br_e)) @ Wl_e + bl_e ----
    gemm_kernel<false><<<dim3(HH / 64, (BB * NN_) / 64, 1), 256>>>(
        p_agg, Wr_e, p_pre, br_e, nullptr, BB * NN_, HH, DD, 0, 0, 0, 0);
    gemm_kernel<false><<<dim3(HH / 64, (BB * NN_) / 64, 1), 256>>>(
        x, Wo_e, p_pre, nullptr, nullptr, BB * NN_, HH, DD, 0, 0, 0, 1);
    normrelu_kernel<<<BB * NN_, 256>>>(p_pre);
    gemm_kernel<false><<<dim3(EE / 64, (BB * NN_) / 64, 1), 256>>>(
        p_pre, Wl_e, out_nodex, bl_e, nullptr, BB * NN_, EE, HH, 0, 0, 0, 0);

    // ---- pool branch -> logits into out_s ----
    gemm_kernel<false><<<dim3(HH / 64, (BB * NN_) / 64, 1), 256>>>(
        p_agg, Wr_p, p_pre, br_p, nullptr, BB * NN_, HH, DD, 0, 0, 0, 0);
    gemm_kernel<false><<<dim3(HH / 64, (BB * NN_) / 64, 1), 256>>>(
        x, Wo_p, p_pre, nullptr, nullptr, BB * NN_, HH, DD, 0, 0, 0, 1);
    normrelu_kernel<<<BB * NN_, 256>>>(p_pre);
    gemm_kernel<false><<<dim3(CC / 64, (BB * NN_) / 64, 1), 256>>>(
        p_pre, Wl_p, out_s, bl_p, nullptr, BB * NN_, CC, HH, 0, 0, 0, 0);

    // softmax, scores, top-k gate (+entropy)
    softmax_kernel<<<BB * NN_, 256>>>(out_s);
    colsum_kernel<<<dim3(8, BB), 256>>>(out_s);
    topk_kernel<<<BB, 256>>>();
    gate_kernel<<<dim3(8, BB), 256>>>(out_s);

    // xp = s^T @ node_x    TN: M=C, Nn=E, K=N
    gemm_kernel<true><<<dim3(EE / 64, CC / 64, BB), 256>>>(
        out_s, out_nodex, out_xp, nullptr, nullptr,
        CC, EE, NN_, (size_t)NN_ * CC, (size_t)NN_ * EE, (size_t)CC * EE, 0);

    // sTa = s^T @ adj      TN: M=C, Nn=N, K=N
    gemm_kernel<true><<<dim3(NN_ / 64, CC / 64, BB), 256>>>(
        out_s, adj, p_sTa, nullptr, nullptr,
        CC, NN_, NN_, (size_t)NN_ * CC, (size_t)NN_ * NN_, (size_t)CC * NN_, 0);

    // adj_p = sTa @ s      NN: M=C, Nn=C, K=N
    gemm_kernel<false><<<dim3(CC / 64, CC / 64, BB), 256>>>(
        p_sTa, out_s, out_adjp, nullptr, nullptr,
        CC, CC, NN_, (size_t)CC * NN_, (size_t)NN_ * CC, (size_t)CC * CC, 0);

    // sts = s^T @ s        TN: M=C, Nn=C, K=N
    gemm_kernel<true><<<dim3(CC / 64, CC / 64, BB), 256>>>(
        out_s, out_s, p_sts, nullptr, nullptr,
        CC, CC, NN_, (size_t)NN_ * CC, (size_t)NN_ * CC, (size_t)CC * CC, 0);

    // U = adj_p @ sts,  V = sts @ adj_p   (for ||S P S^T||^2 = <U, V>)
    gemm_kernel<false><<<dim3(CC / 64, CC / 64, BB), 256>>>(
        out_adjp, p_sts, p_U, nullptr, nullptr,
        CC, CC, CC, (size_t)CC * CC, (size_t)CC * CC, (size_t)CC * CC, 0);
    gemm_kernel<false><<<dim3(CC / 64, CC / 64, BB), 256>>>(
        p_sts, out_adjp, p_V, nullptr, nullptr,
        CC, CC, CC, (size_t)CC * CC, (size_t)CC * CC, (size_t)CC * CC, 0);

    // scalar losses
    sumsq_kernel<<<1024, 256>>>(adj, (size_t)BB * NN_ * NN_);
    batchred_kernel<<<BB, 256>>>(out_adjp);
    final_kernel<<<1, 1>>>(out_scal);
}

// round 4
// speedup vs baseline: 1.0633x; 1.0633x over previous
#include <cuda_runtime.h>
#include <math.h>
#include <stdint.h>

// Problem constants
#define BB   32
#define NN_  1024
#define DD   256
#define HH   256
#define EE   256
#define CC   256
#define KTOP 128
#define TEMPR 0.1f

// ---------------- scratch (device globals; no allocation allowed) ----------------
__device__ float g_deg[BB * NN_];            // 128 KB
__device__ float g_agg[BB * NN_ * DD];       // 32 MB
__device__ float g_pre[BB * NN_ * HH];       // 32 MB
__device__ float g_sTa[BB * CC * NN_];       // 32 MB
__device__ float g_sts[BB * CC * CC];        // 8 MB
__device__ float g_U[BB * CC * CC];          // 8 MB
__device__ float g_V[BB * CC * CC];          // 8 MB
__device__ float g_scores[BB * CC];
__device__ float g_thresh[BB];
__device__ double g_sumsq_adj;
__device__ double g_ent;
__device__ double g_trA[BB], g_ssA[BB], g_trG[BB], g_ssG[BB], g_dotUV[BB];

// ---------------- helpers ----------------
__device__ __forceinline__ double block_red_d(double v, double* sm) {
    int t = threadIdx.x;
    sm[t] = v; __syncthreads();
    for (int o = 128; o > 0; o >>= 1) {
        if (t < o) sm[t] += sm[t + o];
        __syncthreads();
    }
    double r = sm[0]; __syncthreads();
    return r;
}

__global__ void init_kernel() {
    int i = blockIdx.x * blockDim.x + threadIdx.x;
    if (i < BB * CC) g_scores[i] = 0.0f;
    if (i == 0) { g_sumsq_adj = 0.0; g_ent = 0.0; }
}

// degree: deg[b,n] = max(1, sum_m adj[b,n,m])
__global__ void deg_kernel(const float* __restrict__ adj) {
    int row = blockIdx.x;                    // b*N + n
    const float* a = adj + (size_t)row * NN_;
    float s = 0.f;
    for (int i = threadIdx.x; i < NN_; i += 256) s += a[i];
    __shared__ float sm[256];
    sm[threadIdx.x] = s; __syncthreads();
    for (int o = 128; o > 0; o >>= 1) {
        if (threadIdx.x < o) sm[threadIdx.x] += sm[threadIdx.x + o];
        __syncthreads();
    }
    if (threadIdx.x == 0) g_deg[row] = fmaxf(sm[0], 1.0f);
}

// ---------------- 128x128x16 SGEMM, 8x8 microtile ----------------
// C = op(A)@B [+ op2(A2)@B2] [+bias][/rowdiv][+=C]
// TA=false: A is [M,K] row-major (lda=Kd). TA=true: A is [K,M] row-major (lda=M).
// B is [K,N] row-major. M,N multiples of 128; K multiple of 16.
template<bool TA>
__global__ __launch_bounds__(256, 2) void gemm128(
    const float* __restrict__ A, const float* __restrict__ Bm,
    float* __restrict__ Cm,
    const float* __restrict__ A2, const float* __restrict__ B2,
    const float* __restrict__ bias, const float* __restrict__ rowdiv,
    int M, int Nn, int Kd, size_t sA, size_t sB, size_t sC, int beta)
{
    int bz = blockIdx.z;
    int bm = blockIdx.y * 128, bn = blockIdx.x * 128;
    int tid = threadIdx.x, tx = tid & 15, ty = tid >> 4;

    __shared__ float As[16][128];
    __shared__ float Bs[16][128];

    float acc[8][8] = {};

    int nsrc = A2 ? 2 : 1;
    for (int src = 0; src < nsrc; src++) {
        const float* Ap = (src ? A2 : A)  + (size_t)bz * sA;
        const float* Bp = (src ? B2 : Bm) + (size_t)bz * sB;

        for (int k0 = 0; k0 < Kd; k0 += 16) {
            // load A tile -> As[k][m]
            if (TA) {
                #pragma unroll
                for (int i = 0; i < 2; i++) {
                    int id = tid * 2 + i;
                    int r = id >> 5, c4 = id & 31;
                    *(float4*)&As[r][c4 * 4] =
                        *(const float4*)&Ap[(size_t)(k0 + r) * M + bm + c4 * 4];
                }
            } else {
                int row = tid & 127, half = tid >> 7;  // half in {0,1}
                const float* ap = Ap + (size_t)(bm + row) * Kd + k0 + half * 8;
                float4 v0 = *(const float4*)ap;
                float4 v1 = *(const float4*)(ap + 4);
                int kb = half * 8;
                As[kb + 0][row] = v0.x; As[kb + 1][row] = v0.y;
                As[kb + 2][row] = v0.z; As[kb + 3][row] = v0.w;
                As[kb + 4][row] = v1.x; As[kb + 5][row] = v1.y;
                As[kb + 6][row] = v1.z; As[kb + 7][row] = v1.w;
            }
            // load B tile -> Bs[k][n]
            #pragma unroll
            for (int i = 0; i < 2; i++) {
                int id = tid * 2 + i;
                int r = id >> 5, c4 = id & 31;
                *(float4*)&Bs[r][c4 * 4] =
                    *(const float4*)&Bp[(size_t)(k0 + r) * Nn + bn + c4 * 4];
            }
            __syncthreads();

            #pragma unroll
            for (int kk = 0; kk < 16; kk++) {
                float4 a0 = *(const float4*)&As[kk][ty * 4];
                float4 a1 = *(const float4*)&As[kk][64 + ty * 4];
                float4 b0 = *(const float4*)&Bs[kk][tx * 4];
                float4 b1 = *(const float4*)&Bs[kk][64 + tx * 4];
                float av[8] = {a0.x, a0.y, a0.z, a0.w, a1.x, a1.y, a1.z, a1.w};
                float bv[8] = {b0.x, b0.y, b0.z, b0.w, b1.x, b1.y, b1.z, b1.w};
                #pragma unroll
                for (int i = 0; i < 8; i++)
                    #pragma unroll
                    for (int j = 0; j < 8; j++)
                        acc[i][j] += av[i] * bv[j];
            }
            __syncthreads();
        }
    }

    float* Cp = Cm + (size_t)bz * sC;
    #pragma unroll
    for (int ih = 0; ih < 2; ih++) {
        #pragma unroll
        for (int i = 0; i < 4; i++) {
            int m = bm + ih * 64 + ty * 4 + i;
            float inv = 1.0f;
            if (rowdiv) inv = 1.0f / rowdiv[(size_t)bz * M + m];
            #pragma unroll
            for (int jh = 0; jh < 2; jh++) {
                int n = bn + jh * 64 + tx * 4;
                float4 v;
                v.x = acc[ih * 4 + i][jh * 4 + 0];
                v.y = acc[ih * 4 + i][jh * 4 + 1];
                v.z = acc[ih * 4 + i][jh * 4 + 2];
                v.w = acc[ih * 4 + i][jh * 4 + 3];
                if (rowdiv) { v.x *= inv; v.y *= inv; v.z *= inv; v.w *= inv; }
                if (bias) {
                    const float4 bb = *(const float4*)&bias[n];
                    v.x += bb.x; v.y += bb.y; v.z += bb.z; v.w += bb.w;
                }
                size_t idx = (size_t)m * Nn + n;
                if (beta) {
                    float4 c0 = *(const float4*)&Cp[idx];
                    v.x += c0.x; v.y += c0.y; v.z += c0.z; v.w += c0.w;
                }
                *(float4*)&Cp[idx] = v;
            }
        }
    }
}

// l2-normalize row (len 256) then relu, in place
__global__ void normrelu_kernel(float* __restrict__ p) {
    size_t row = blockIdx.x;
    float* r = p + row * HH;
    float v = r[threadIdx.x];
    __shared__ float sm[256];
    sm[threadIdx.x] = v * v; __syncthreads();
    for (int o = 128; o > 0; o >>= 1) {
        if (threadIdx.x < o) sm[threadIdx.x] += sm[threadIdx.x + o];
        __syncthreads();
    }
    float nrm = fmaxf(sqrtf(sm[0]), 1e-12f);
    r[threadIdx.x] = fmaxf(v, 0.0f) / nrm;
}

// softmax over last dim (256), in place
__global__ void softmax_kernel(float* __restrict__ s) {
    size_t row = blockIdx.x;
    float* r = s + row * CC;
    float v = r[threadIdx.x];
    __shared__ float sm[256];
    sm[threadIdx.x] = v; __syncthreads();
    for (int o = 128; o > 0; o >>= 1) {
        if (threadIdx.x < o) sm[threadIdx.x] = fmaxf(sm[threadIdx.x], sm[threadIdx.x + o]);
        __syncthreads();
    }
    float mx = sm[0]; __syncthreads();
    float e = expf(v - mx);
    sm[threadIdx.x] = e; __syncthreads();
    for (int o = 128; o > 0; o >>= 1) {
        if (threadIdx.x < o) sm[threadIdx.x] += sm[threadIdx.x + o];
        __syncthreads();
    }
    r[threadIdx.x] = e / sm[0];
}

// scores[b,c] = sum_n s[b,n,c]   grid: (8, B)
__global__ void colsum_kernel(const float* __restrict__ s) {
    int b = blockIdx.y;
    const float* base = s + ((size_t)b * NN_ + (size_t)blockIdx.x * 128) * CC;
    float acc = 0.f;
    for (int r = 0; r < 128; r++) acc += base[(size_t)r * CC + threadIdx.x];
    atomicAdd(&g_scores[b * CC + threadIdx.x], acc);
}

// thresh[b] = K-th largest of scores[b,:]
__global__ void topk_kernel() {
    int b = blockIdx.x, t = threadIdx.x;
    __shared__ float sm[256];
    sm[t] = g_scores[b * CC + t]; __syncthreads();
    float v = sm[t];
    int cnt = 0;
    for (int j = 0; j < CC; j++) {
        float w = sm[j];
        cnt += (w > v) || (w == v && j < t);
    }
    if (cnt == KTOP - 1) g_thresh[b] = v;
}

// s *= sigmoid((scores - thresh)/T), accumulate entropy   grid: (8, B)
__global__ void gate_kernel(float* __restrict__ s) {
    int b = blockIdx.y, t = threadIdx.x;
    float xg = (g_scores[b * CC + t] - g_thresh[b]) / TEMPR;
    float gt;
    if (xg >= 0.f) gt = 1.0f / (1.0f + expf(-xg));
    else { float ex = expf(xg); gt = ex / (1.0f + ex); }
    float* base = s + ((size_t)b * NN_ + (size_t)blockIdx.x * 128) * CC;
    double e = 0.0;
    for (int r = 0; r < 128; r++) {
        size_t idx = (size_t)r * CC + t;
        float v = base[idx] * gt;
        base[idx] = v;
        e += (double)(-v * logf(v + 1e-15f));
    }
    __shared__ double sm[256];
    double tot = block_red_d(e, sm);
    if (t == 0) atomicAdd(&g_ent, tot);
}

// global sum of adj^2 (double)
__global__ void sumsq_kernel(const float* __restrict__ adj, size_t n) {
    double acc = 0.0;
    for (size_t i = (size_t)blockIdx.x * blockDim.x + threadIdx.x; i < n;
         i += (size_t)gridDim.x * blockDim.x) {
        float v = adj[i];
        acc += (double)v * v;
    }
    __shared__ double sm[256];
    double tot = block_red_d(acc, sm);
    if (threadIdx.x == 0) atomicAdd(&g_sumsq_adj, tot);
}

// per-batch traces / frobenius sums over [C,C] mats: adj_p, sts, U.V
__global__ void batchred_kernel(const float* __restrict__ adjp) {
    int b = blockIdx.x, t = threadIdx.x;
    const float* P = adjp  + (size_t)b * CC * CC;
    const float* G = g_sts + (size_t)b * CC * CC;
    const float* U = g_U   + (size_t)b * CC * CC;
    const float* V = g_V   + (size_t)b * CC * CC;
    double trA = 0, ssA = 0, trG = 0, ssG = 0, duv = 0;
    for (int i = t; i < CC * CC; i += 256) {
        float p = P[i]; ssA += (double)p * p;
        float g = G[i]; ssG += (double)g * g;
        duv += (double)U[i] * (double)V[i];
        if (i % (CC + 1) == 0) { trA += p; trG += g; }
    }
    __shared__ double sm[256];
    double r;
    r = block_red_d(trA, sm); if (t == 0) g_trA[b] = r;
    r = block_red_d(ssA, sm); if (t == 0) g_ssA[b] = r;
    r = block_red_d(trG, sm); if (t == 0) g_trG[b] = r;
    r = block_red_d(ssG, sm); if (t == 0) g_ssG[b] = r;
    r = block_red_d(duv, sm); if (t == 0) g_dotUV[b] = r;
}

// final scalars: link, ent, clu, recon
__global__ void final_kernel(float* __restrict__ o) {
    double linksq = g_sumsq_adj, reconsq = g_sumsq_adj, clusum = 0.0;
    for (int b = 0; b < BB; b++) {
        linksq  += -2.0 * g_trA[b] + g_ssG[b];
        reconsq += -2.0 * g_ssA[b] + g_dotUV[b];
        double nrm = sqrt(g_ssG[b]); if (nrm < 1e-12) nrm = 1e-12;
        double t1 = g_ssG[b] / (nrm * nrm);
        double cb = t1 - 2.0 * g_trG[b] / (nrm * 16.0) + 1.0;   // sqrt(C)=16
        clusum += sqrt(cb > 0.0 ? cb : 0.0);
    }
    double sz = (double)BB * NN_ * NN_;
    o[0] = (float)(sqrt(linksq  > 0.0 ? linksq  : 0.0) / sz);  // link
    o[1] = (float)(g_ent / ((double)BB * NN_));                // ent
    o[2] = (float)(clusum / BB);                               // clu
    o[3] = (float)(sqrt(reconsq > 0.0 ? reconsq : 0.0) / sz);  // recon
}

// ---------------- launch ----------------
extern "C" void kernel_launch(void* const* d_in, const int* in_sizes, int n_in,
                              void* d_out, int out_size) {
    const float* x    = (const float*)d_in[0];
    const float* adj  = (const float*)d_in[1];
    const float* Wr_p = (const float*)d_in[2];
    const float* br_p = (const float*)d_in[3];
    const float* Wo_p = (const float*)d_in[4];
    const float* Wl_p = (const float*)d_in[5];
    const float* bl_p = (const float*)d_in[6];
    const float* Wr_e = (const float*)d_in[7];
    const float* br_e = (const float*)d_in[8];
    const float* Wo_e = (const float*)d_in[9];
    const float* Wl_e = (const float*)d_in[10];
    const float* bl_e = (const float*)d_in[11];

    float* out       = (float*)d_out;
    float* out_xp    = out;                         // [B,C,E]
    float* out_adjp  = out + 2097152;               // [B,C,C]
    float* out_s     = out + 4194304;               // [B,N,C]
    float* out_scal  = out + 12582912;              // link, ent, clu, recon
    float* out_nodex = out + 12582916;              // [B,N,E]

    float *p_deg, *p_agg, *p_pre, *p_sTa, *p_sts, *p_U, *p_V;
    cudaGetSymbolAddress((void**)&p_deg, g_deg);
    cudaGetSymbolAddress((void**)&p_agg, g_agg);
    cudaGetSymbolAddress((void**)&p_pre, g_pre);
    cudaGetSymbolAddress((void**)&p_sTa, g_sTa);
    cudaGetSymbolAddress((void**)&p_sts, g_sts);
    cudaGetSymbolAddress((void**)&p_U,   g_U);
    cudaGetSymbolAddress((void**)&p_V,   g_V);

    init_kernel<<<32, 256>>>();
    deg_kernel<<<BB * NN_, 256>>>(adj);

    // agg = (adj @ x) / deg   batched: M=1024, N=D, K=1024
    gemm128<false><<<dim3(DD / 128, NN_ / 128, BB), 256>>>(
        adj, x, p_agg, nullptr, nullptr, nullptr, p_deg,
        NN_, DD, NN_, (size_t)NN_ * NN_, (size_t)NN_ * DD, (size_t)NN_ * DD, 0);

    // ---- embed branch: pre = agg@Wr_e + x@Wo_e + br_e (fused dual-source) ----
    gemm128<false><<<dim3(HH / 128, (BB * NN_) / 128, 1), 256>>>(
        p_agg, Wr_e, p_pre, x, Wo_e, br_e, nullptr,
        BB * NN_, HH, DD, 0, 0, 0, 0);
    normrelu_kernel<<<BB * NN_, 256>>>(p_pre);
    gemm128<false><<<dim3(EE / 128, (BB * NN_) / 128, 1), 256>>>(
        p_pre, Wl_e, out_nodex, nullptr, nullptr, bl_e, nullptr,
        BB * NN_, EE, HH, 0, 0, 0, 0);

    // ---- pool branch -> logits into out_s ----
    gemm128<false><<<dim3(HH / 128, (BB * NN_) / 128, 1), 256>>>(
        p_agg, Wr_p, p_pre, x, Wo_p, br_p, nullptr,
        BB * NN_, HH, DD, 0, 0, 0, 0);
    normrelu_kernel<<<BB * NN_, 256>>>(p_pre);
    gemm128<false><<<dim3(CC / 128, (BB * NN_) / 128, 1), 256>>>(
        p_pre, Wl_p, out_s, nullptr, nullptr, bl_p, nullptr,
        BB * NN_, CC, HH, 0, 0, 0, 0);

    // softmax, scores, top-k gate (+entropy)
    softmax_kernel<<<BB * NN_, 256>>>(out_s);
    colsum_kernel<<<dim3(8, BB), 256>>>(out_s);
    topk_kernel<<<BB, 256>>>();
    gate_kernel<<<dim3(8, BB), 256>>>(out_s);

    // xp = s^T @ node_x    TN: M=C, N=E, K=N
    gemm128<true><<<dim3(EE / 128, CC / 128, BB), 256>>>(
        out_s, out_nodex, out_xp, nullptr, nullptr, nullptr, nullptr,
        CC, EE, NN_, (size_t)NN_ * CC, (size_t)NN_ * EE, (size_t)CC * EE, 0);

    // sTa = s^T @ adj      TN: M=C, N=N, K=N
    gemm128<true><<<dim3(NN_ / 128, CC / 128, BB), 256>>>(
        out_s, adj, p_sTa, nullptr, nullptr, nullptr, nullptr,
        CC, NN_, NN_, (size_t)NN_ * CC, (size_t)NN_ * NN_, (size_t)CC * NN_, 0);

    // adj_p = sTa @ s      NN: M=C, N=C, K=N
    gemm128<false><<<dim3(CC / 128, CC / 128, BB), 256>>>(
        p_sTa, out_s, out_adjp, nullptr, nullptr, nullptr, nullptr,
        CC, CC, NN_, (size_t)CC * NN_, (size_t)NN_ * CC, (size_t)CC * CC, 0);

    // sts = s^T @ s        TN: M=C, N=C, K=N
    gemm128<true><<<dim3(CC / 128, CC / 128, BB), 256>>>(
        out_s, out_s, p_sts, nullptr, nullptr, nullptr, nullptr,
        CC, CC, NN_, (size_t)NN_ * CC, (size_t)NN_ * CC, (size_t)CC * CC, 0);

    // U = adj_p @ sts,  V = sts @ adj_p   (for ||S P S^T||^2 = <U, V>)
    gemm128<false><<<dim3(CC / 128, CC / 128, BB), 256>>>(
        out_adjp, p_sts, p_U, nullptr, nullptr, nullptr, nullptr,
        CC, CC, CC, (size_t)CC * CC, (size_t)CC * CC, (size_t)CC * CC, 0);
    gemm128<false><<<dim3(CC / 128, CC / 128, BB), 256>>>(
        p_sts, out_adjp, p_V, nullptr, nullptr, nullptr, nullptr,
        CC, CC, CC, (size_t)CC * CC, (size_t)CC * CC, (size_t)CC * CC, 0);

    // scalar losses
    sumsq_kernel<<<1024, 256>>>(adj, (size_t)BB * NN_ * NN_);
    batchred_kernel<<<BB, 256>>>(out_adjp);
    final_kernel<<<1, 1>>>(out_scal);
}

// round 5
// speedup vs baseline: 1.1642x; 1.0949x over previous
#include <cuda_runtime.h>
#include <math.h>
#include <stdint.h>

// Problem constants
#define BB   32
#define NN_  1024
#define DD   256
#define HH   256
#define EE   256
#define CC   256
#define KTOP 128
#define TEMPR 0.1f

// ---------------- scratch (device globals; no allocation allowed) ----------------
__device__ float g_deg[BB * NN_];
__device__ float g_agg[BB * NN_ * DD];       // 32 MB
__device__ float g_pre[BB * NN_ * HH];       // 32 MB
__device__ float g_sTa[BB * CC * NN_];       // 32 MB
__device__ float g_sts[BB * CC * CC];        // 8 MB
__device__ float g_U[BB * CC * CC];          // 8 MB
__device__ float g_V[BB * CC * CC];          // 8 MB
__device__ float g_scores[BB * CC];
__device__ float g_thresh[BB];
__device__ double g_sumsq_adj;
__device__ double g_ent;
__device__ double g_trA[BB], g_ssA[BB], g_trG[BB], g_ssG[BB], g_dotUV[BB];

// ---------------- helpers ----------------
__device__ __forceinline__ double block_red_d(double v, double* sm) {
    int t = threadIdx.x;
    sm[t] = v; __syncthreads();
    for (int o = 128; o > 0; o >>= 1) {
        if (t < o) sm[t] += sm[t + o];
        __syncthreads();
    }
    double r = sm[0]; __syncthreads();
    return r;
}

__device__ __forceinline__ void cp16(void* s, const void* g) {
    uint32_t si = (uint32_t)__cvta_generic_to_shared(s);
    asm volatile("cp.async.cg.shared.global [%0], [%1], 16;\n" :: "r"(si), "l"(g));
}
__device__ __forceinline__ void cp_commit() {
    asm volatile("cp.async.commit_group;\n" ::);
}

__global__ void init_kernel() {
    int i = blockIdx.x * blockDim.x + threadIdx.x;
    if (i < BB * CC) g_scores[i] = 0.0f;
    if (i == 0) { g_sumsq_adj = 0.0; g_ent = 0.0; }
}

// degree: deg[b,n] = max(1, sum_m adj[b,n,m])
__global__ void deg_kernel(const float* __restrict__ adj) {
    int row = blockIdx.x;
    const float* a = adj + (size_t)row * NN_;
    float s = 0.f;
    for (int i = threadIdx.x; i < NN_; i += 256) s += a[i];
    __shared__ float sm[256];
    sm[threadIdx.x] = s; __syncthreads();
    for (int o = 128; o > 0; o >>= 1) {
        if (threadIdx.x < o) sm[threadIdx.x] += sm[threadIdx.x + o];
        __syncthreads();
    }
    if (threadIdx.x == 0) g_deg[row] = fmaxf(sm[0], 1.0f);
}

// ---------------- pipelined 128x128x16 SGEMM, 8x8 microtile, cp.async ----------------
// C = op(A)@B [+ op2(A2)@B2] [+bias][/rowdiv]
// TA=false: A is [M,K] row-major. TA=true: A is [K,M] row-major.
// B is [K,N] row-major. M,N multiples of 128; K multiple of 16.
template<bool TA>
__global__ __launch_bounds__(256, 2) void gemm128(
    const float* __restrict__ A, const float* __restrict__ Bm,
    float* __restrict__ Cm,
    const float* __restrict__ A2, const float* __restrict__ B2,
    const float* __restrict__ bias, const float* __restrict__ rowdiv,
    int M, int Nn, int Kd, size_t sA, size_t sB, size_t sC)
{
    constexpr int ASZ = TA ? (16 * 128) : (128 * 20);
    __shared__ float As[2][ASZ];
    __shared__ float Bs[2][16 * 128];

    int bz = blockIdx.z;
    int bm = blockIdx.y * 128, bn = blockIdx.x * 128;
    int tid = threadIdx.x, tx = tid & 15, ty = tid >> 4;

    const float* Ab1 = A  + (size_t)bz * sA;
    const float* Bb1 = Bm + (size_t)bz * sB;
    const float* Ab2 = A2 ? A2 + (size_t)bz * sA : nullptr;
    const float* Bb2 = A2 ? B2 + (size_t)bz * sB : nullptr;
    const int T1 = Kd / 16;
    const int T  = A2 ? 2 * T1 : T1;

    auto issue = [&](int t, int buf) {
        const float* Ap; const float* Bp; int k0;
        if (t < T1) { Ap = Ab1; Bp = Bb1; k0 = t * 16; }
        else        { Ap = Ab2; Bp = Bb2; k0 = (t - T1) * 16; }
        // B tile: [16][128] row-contiguous
        #pragma unroll
        for (int i = 0; i < 2; i++) {
            int id = tid * 2 + i;
            int r = id >> 5, c = (id & 31) * 4;
            cp16(&Bs[buf][r * 128 + c], Bp + (size_t)(k0 + r) * Nn + bn + c);
        }
        if (TA) {
            #pragma unroll
            for (int i = 0; i < 2; i++) {
                int id = tid * 2 + i;
                int r = id >> 5, c = (id & 31) * 4;
                cp16(&As[buf][r * 128 + c], Ap + (size_t)(k0 + r) * M + bm + c);
            }
        } else {
            // A tile row-major [128][20] (pitch 20 floats = 80B, 16B-aligned chunks)
            #pragma unroll
            for (int i = 0; i < 2; i++) {
                int id = tid * 2 + i;
                int row = id >> 2, ch = (id & 3) * 4;
                cp16(&As[buf][row * 20 + ch], Ap + (size_t)(bm + row) * Kd + k0 + ch);
            }
        }
        cp_commit();
    };

    float acc[8][8] = {};

    issue(0, 0);
    issue(1, 1);

    for (int t = 0; t < T; t++) {
        if (t + 1 < T) asm volatile("cp.async.wait_group 1;\n" ::);
        else           asm volatile("cp.async.wait_group 0;\n" ::);
        __syncthreads();

        const float* as = As[t & 1];
        const float* bs = Bs[t & 1];

        if (TA) {
            #pragma unroll
            for (int kk = 0; kk < 16; kk++) {
                float4 a0 = *(const float4*)&as[kk * 128 + ty * 4];
                float4 a1 = *(const float4*)&as[kk * 128 + 64 + ty * 4];
                float4 b0 = *(const float4*)&bs[kk * 128 + tx * 4];
                float4 b1 = *(const float4*)&bs[kk * 128 + 64 + tx * 4];
                float av[8] = {a0.x, a0.y, a0.z, a0.w, a1.x, a1.y, a1.z, a1.w};
                float bv[8] = {b0.x, b0.y, b0.z, b0.w, b1.x, b1.y, b1.z, b1.w};
                #pragma unroll
                for (int i = 0; i < 8; i++)
                    #pragma unroll
                    for (int j = 0; j < 8; j++)
                        acc[i][j] += av[i] * bv[j];
            }
        } else {
            #pragma unroll
            for (int kg = 0; kg < 8; kg++) {          // 2 k-steps per group
                float2 a2[8];
                #pragma unroll
                for (int i = 0; i < 4; i++) {
                    a2[i]     = *(const float2*)&as[(ty * 4 + i) * 20 + kg * 2];
                    a2[4 + i] = *(const float2*)&as[(64 + ty * 4 + i) * 20 + kg * 2];
                }
                #pragma unroll
                for (int kk = 0; kk < 2; kk++) {
                    int k = kg * 2 + kk;
                    float4 b0 = *(const float4*)&bs[k * 128 + tx * 4];
                    float4 b1 = *(const float4*)&bs[k * 128 + 64 + tx * 4];
                    float bv[8] = {b0.x, b0.y, b0.z, b0.w, b1.x, b1.y, b1.z, b1.w};
                    float av[8];
                    #pragma unroll
                    for (int i = 0; i < 8; i++)
                        av[i] = kk ? a2[i].y : a2[i].x;
                    #pragma unroll
                    for (int i = 0; i < 8; i++)
                        #pragma unroll
                        for (int j = 0; j < 8; j++)
                            acc[i][j] += av[i] * bv[j];
                }
            }
        }
        __syncthreads();
        if (t + 2 < T) issue(t + 2, t & 1);
    }

    float* Cp = Cm + (size_t)bz * sC;
    #pragma unroll
    for (int ih = 0; ih < 2; ih++) {
        #pragma unroll
        for (int i = 0; i < 4; i++) {
            int m = bm + ih * 64 + ty * 4 + i;
            float inv = 1.0f;
            if (rowdiv) inv = 1.0f / rowdiv[(size_t)bz * M + m];
            #pragma unroll
            for (int jh = 0; jh < 2; jh++) {
                int n = bn + jh * 64 + tx * 4;
                float4 v;
                v.x = acc[ih * 4 + i][jh * 4 + 0];
                v.y = acc[ih * 4 + i][jh * 4 + 1];
                v.z = acc[ih * 4 + i][jh * 4 + 2];
                v.w = acc[ih * 4 + i][jh * 4 + 3];
                if (rowdiv) { v.x *= inv; v.y *= inv; v.z *= inv; v.w *= inv; }
                if (bias) {
                    const float4 bb = *(const float4*)&bias[n];
                    v.x += bb.x; v.y += bb.y; v.z += bb.z; v.w += bb.w;
                }
                *(float4*)&Cp[(size_t)m * Nn + n] = v;
            }
        }
    }
}

// l2-normalize row (len 256) then relu, in place
__global__ void normrelu_kernel(float* __restrict__ p) {
    size_t row = blockIdx.x;
    float* r = p + row * HH;
    float v = r[threadIdx.x];
    __shared__ float sm[256];
    sm[threadIdx.x] = v * v; __syncthreads();
    for (int o = 128; o > 0; o >>= 1) {
        if (threadIdx.x < o) sm[threadIdx.x] += sm[threadIdx.x + o];
        __syncthreads();
    }
    float nrm = fmaxf(sqrtf(sm[0]), 1e-12f);
    r[threadIdx.x] = fmaxf(v, 0.0f) / nrm;
}

// softmax over last dim (256), in place
__global__ void softmax_kernel(float* __restrict__ s) {
    size_t row = blockIdx.x;
    float* r = s + row * CC;
    float v = r[threadIdx.x];
    __shared__ float sm[256];
    sm[threadIdx.x] = v; __syncthreads();
    for (int o = 128; o > 0; o >>= 1) {
        if (threadIdx.x < o) sm[threadIdx.x] = fmaxf(sm[threadIdx.x], sm[threadIdx.x + o]);
        __syncthreads();
    }
    float mx = sm[0]; __syncthreads();
    float e = expf(v - mx);
    sm[threadIdx.x] = e; __syncthreads();
    for (int o = 128; o > 0; o >>= 1) {
        if (threadIdx.x < o) sm[threadIdx.x] += sm[threadIdx.x + o];
        __syncthreads();
    }
    r[threadIdx.x] = e / sm[0];
}

// scores[b,c] = sum_n s[b,n,c]   grid: (8, B)
__global__ void colsum_kernel(const float* __restrict__ s) {
    int b = blockIdx.y;
    const float* base = s + ((size_t)b * NN_ + (size_t)blockIdx.x * 128) * CC;
    float acc = 0.f;
    for (int r = 0; r < 128; r++) acc += base[(size_t)r * CC + threadIdx.x];
    atomicAdd(&g_scores[b * CC + threadIdx.x], acc);
}

// thresh[b] = K-th largest of scores[b,:]
__global__ void topk_kernel() {
    int b = blockIdx.x, t = threadIdx.x;
    __shared__ float sm[256];
    sm[t] = g_scores[b * CC + t]; __syncthreads();
    float v = sm[t];
    int cnt = 0;
    for (int j = 0; j < CC; j++) {
        float w = sm[j];
        cnt += (w > v) || (w == v && j < t);
    }
    if (cnt == KTOP - 1) g_thresh[b] = v;
}

// s *= sigmoid((scores - thresh)/T), accumulate entropy   grid: (8, B)
__global__ void gate_kernel(float* __restrict__ s) {
    int b = blockIdx.y, t = threadIdx.x;
    float xg = (g_scores[b * CC + t] - g_thresh[b]) / TEMPR;
    float gt;
    if (xg >= 0.f) gt = 1.0f / (1.0f + expf(-xg));
    else { float ex = expf(xg); gt = ex / (1.0f + ex); }
    float* base = s + ((size_t)b * NN_ + (size_t)blockIdx.x * 128) * CC;
    double e = 0.0;
    for (int r = 0; r < 128; r++) {
        size_t idx = (size_t)r * CC + t;
        float v = base[idx] * gt;
        base[idx] = v;
        e += (double)(-v * logf(v + 1e-15f));
    }
    __shared__ double sm[256];
    double tot = block_red_d(e, sm);
    if (t == 0) atomicAdd(&g_ent, tot);
}

// global sum of adj^2 (double)
__global__ void sumsq_kernel(const float* __restrict__ adj, size_t n) {
    double acc = 0.0;
    for (size_t i = (size_t)blockIdx.x * blockDim.x + threadIdx.x; i < n;
         i += (size_t)gridDim.x * blockDim.x) {
        float v = adj[i];
        acc += (double)v * v;
    }
    __shared__ double sm[256];
    double tot = block_red_d(acc, sm);
    if (threadIdx.x == 0) atomicAdd(&g_sumsq_adj, tot);
}

// per-batch traces / frobenius sums over [C,C] mats
__global__ void batchred_kernel(const float* __restrict__ adjp) {
    int b = blockIdx.x, t = threadIdx.x;
    const float* P = adjp  + (size_t)b * CC * CC;
    const float* G = g_sts + (size_t)b * CC * CC;
    const float* U = g_U   + (size_t)b * CC * CC;
    const float* V = g_V   + (size_t)b * CC * CC;
    double trA = 0, ssA = 0, trG = 0, ssG = 0, duv = 0;
    for (int i = t; i < CC * CC; i += 256) {
        float p = P[i]; ssA += (double)p * p;
        float g = G[i]; ssG += (double)g * g;
        duv += (double)U[i] * (double)V[i];
        if (i % (CC + 1) == 0) { trA += p; trG += g; }
    }
    __shared__ double sm[256];
    double r;
    r = block_red_d(trA, sm); if (t == 0) g_trA[b] = r;
    r = block_red_d(ssA, sm); if (t == 0) g_ssA[b] = r;
    r = block_red_d(trG, sm); if (t == 0) g_trG[b] = r;
    r = block_red_d(ssG, sm); if (t == 0) g_ssG[b] = r;
    r = block_red_d(duv, sm); if (t == 0) g_dotUV[b] = r;
}

// final scalars: link, ent, clu, recon
__global__ void final_kernel(float* __restrict__ o) {
    double linksq = g_sumsq_adj, reconsq = g_sumsq_adj, clusum = 0.0;
    for (int b = 0; b < BB; b++) {
        linksq  += -2.0 * g_trA[b] + g_ssG[b];
        reconsq += -2.0 * g_ssA[b] + g_dotUV[b];
        double nrm = sqrt(g_ssG[b]); if (nrm < 1e-12) nrm = 1e-12;
        double t1 = g_ssG[b] / (nrm * nrm);
        double cb = t1 - 2.0 * g_trG[b] / (nrm * 16.0) + 1.0;   // sqrt(C)=16
        clusum += sqrt(cb > 0.0 ? cb : 0.0);
    }
    double sz = (double)BB * NN_ * NN_;
    o[0] = (float)(sqrt(linksq  > 0.0 ? linksq  : 0.0) / sz);  // link
    o[1] = (float)(g_ent / ((double)BB * NN_));                // ent
    o[2] = (float)(clusum / BB);                               // clu
    o[3] = (float)(sqrt(reconsq > 0.0 ? reconsq : 0.0) / sz);  // recon
}

// ---------------- launch ----------------
extern "C" void kernel_launch(void* const* d_in, const int* in_sizes, int n_in,
                              void* d_out, int out_size) {
    const float* x    = (const float*)d_in[0];
    const float* adj  = (const float*)d_in[1];
    const float* Wr_p = (const float*)d_in[2];
    const float* br_p = (const float*)d_in[3];
    const float* Wo_p = (const float*)d_in[4];
    const float* Wl_p = (const float*)d_in[5];
    const float* bl_p = (const float*)d_in[6];
    const float* Wr_e = (const float*)d_in[7];
    const float* br_e = (const float*)d_in[8];
    const float* Wo_e = (const float*)d_in[9];
    const float* Wl_e = (const float*)d_in[10];
    const float* bl_e = (const float*)d_in[11];

    float* out       = (float*)d_out;
    float* out_xp    = out;                         // [B,C,E]
    float* out_adjp  = out + 2097152;               // [B,C,C]
    float* out_s     = out + 4194304;               // [B,N,C]
    float* out_scal  = out + 12582912;              // link, ent, clu, recon
    float* out_nodex = out + 12582916;              // [B,N,E]

    float *p_deg, *p_agg, *p_pre, *p_sTa, *p_sts, *p_U, *p_V;
    cudaGetSymbolAddress((void**)&p_deg, g_deg);
    cudaGetSymbolAddress((void**)&p_agg, g_agg);
    cudaGetSymbolAddress((void**)&p_pre, g_pre);
    cudaGetSymbolAddress((void**)&p_sTa, g_sTa);
    cudaGetSymbolAddress((void**)&p_sts, g_sts);
    cudaGetSymbolAddress((void**)&p_U,   g_U);
    cudaGetSymbolAddress((void**)&p_V,   g_V);

    init_kernel<<<32, 256>>>();
    deg_kernel<<<BB * NN_, 256>>>(adj);

    // agg = (adj @ x) / deg   batched: M=1024, N=D, K=1024
    gemm128<false><<<dim3(DD / 128, NN_ / 128, BB), 256>>>(
        adj, x, p_agg, nullptr, nullptr, nullptr, p_deg,
        NN_, DD, NN_, (size_t)NN_ * NN_, (size_t)NN_ * DD, (size_t)NN_ * DD);

    // ---- embed branch: pre = agg@Wr_e + x@Wo_e + br_e (fused dual-source) ----
    gemm128<false><<<dim3(HH / 128, (BB * NN_) / 128, 1), 256>>>(
        p_agg, Wr_e, p_pre, x, Wo_e, br_e, nullptr,
        BB * NN_, HH, DD, 0, 0, 0);
    normrelu_kernel<<<BB * NN_, 256>>>(p_pre);
    gemm128<false><<<dim3(EE / 128, (BB * NN_) / 128, 1), 256>>>(
        p_pre, Wl_e, out_nodex, nullptr, nullptr, bl_e, nullptr,
        BB * NN_, EE, HH, 0, 0, 0);

    // ---- pool branch -> logits into out_s ----
    gemm128<false><<<dim3(HH / 128, (BB * NN_) / 128, 1), 256>>>(
        p_agg, Wr_p, p_pre, x, Wo_p, br_p, nullptr,
        BB * NN_, HH, DD, 0, 0, 0);
    normrelu_kernel<<<BB * NN_, 256>>>(p_pre);
    gemm128<false><<<dim3(CC / 128, (BB * NN_) / 128, 1), 256>>>(
        p_pre, Wl_p, out_s, nullptr, nullptr, bl_p, nullptr,
        BB * NN_, CC, HH, 0, 0, 0);

    // softmax, scores, top-k gate (+entropy)
    softmax_kernel<<<BB * NN_, 256>>>(out_s);
    colsum_kernel<<<dim3(8, BB), 256>>>(out_s);
    topk_kernel<<<BB, 256>>>();
    gate_kernel<<<dim3(8, BB), 256>>>(out_s);

    // xp = s^T @ node_x    TN: M=C, N=E, K=N
    gemm128<true><<<dim3(EE / 128, CC / 128, BB), 256>>>(
        out_s, out_nodex, out_xp, nullptr, nullptr, nullptr, nullptr,
        CC, EE, NN_, (size_t)NN_ * CC, (size_t)NN_ * EE, (size_t)CC * EE);

    // sTa = s^T @ adj      TN: M=C, N=N, K=N
    gemm128<true><<<dim3(NN_ / 128, CC / 128, BB), 256>>>(
        out_s, adj, p_sTa, nullptr, nullptr, nullptr, nullptr,
        CC, NN_, NN_, (size_t)NN_ * CC, (size_t)NN_ * NN_, (size_t)CC * NN_);

    // adj_p = sTa @ s      NN: M=C, N=C, K=N
    gemm128<false><<<dim3(CC / 128, CC / 128, BB), 256>>>(
        p_sTa, out_s, out_adjp, nullptr, nullptr, nullptr, nullptr,
        CC, CC, NN_, (size_t)CC * NN_, (size_t)NN_ * CC, (size_t)CC * CC);

    // sts = s^T @ s        TN: M=C, N=C, K=N
    gemm128<true><<<dim3(CC / 128, CC / 128, BB), 256>>>(
        out_s, out_s, p_sts, nullptr, nullptr, nullptr, nullptr,
        CC, CC, NN_, (size_t)NN_ * CC, (size_t)NN_ * CC, (size_t)CC * CC);

    // U = adj_p @ sts,  V = sts @ adj_p   (for ||S P S^T||^2 = <U, V>)
    gemm128<false><<<dim3(CC / 128, CC / 128, BB), 256>>>(
        out_adjp, p_sts, p_U, nullptr, nullptr, nullptr, nullptr,
        CC, CC, CC, (size_t)CC * CC, (size_t)CC * CC, (size_t)CC * CC);
    gemm128<false><<<dim3(CC / 128, CC / 128, BB), 256>>>(
        p_sts, out_adjp, p_V, nullptr, nullptr, nullptr, nullptr,
        CC, CC, CC, (size_t)CC * CC, (size_t)CC * CC, (size_t)CC * CC);

    // scalar losses
    sumsq_kernel<<<1024, 256>>>(adj, (size_t)BB * NN_ * NN_);
    batchred_kernel<<<BB, 256>>>(out_adjp);
    final_kernel<<<1, 1>>>(out_scal);
}